// round 14
// baseline (speedup 1.0000x reference)
#include <cuda_runtime.h>
#include <cuda_bf16.h>
#include <cstdint>

#define DDIM 256
#define KREF 32
#define MT   256    // rows per CTA (8 warps x m32)

// ---------------- device scratch (no allocation) ----------------
__device__ __align__(16) __nv_bfloat16 g_Uh[KREF * DDIM];   // [k][d]
__device__ __align__(16) __nv_bfloat16 g_Ul[KREF * DDIM];
__device__ __align__(16) __nv_bfloat16 g_Qh[DDIM * KREF];   // [d][k]
__device__ __align__(16) __nv_bfloat16 g_Ql[DDIM * KREF];

// ---------------- helpers ----------------
__device__ __forceinline__ uint32_t smem_u32(const void* p) {
    uint32_t a;
    asm("{ .reg .u64 t; cvta.to.shared.u64 t, %1; cvt.u32.u64 %0, t; }" : "=r"(a) : "l"(p));
    return a;
}
__device__ __forceinline__ void ldsm4(uint32_t& r0, uint32_t& r1, uint32_t& r2, uint32_t& r3,
                                      uint32_t addr) {
    asm volatile("ldmatrix.sync.aligned.m8n8.x4.shared.b16 {%0,%1,%2,%3}, [%4];"
                 : "=r"(r0), "=r"(r1), "=r"(r2), "=r"(r3) : "r"(addr));
}
__device__ __forceinline__ void mma16816(float* d, const uint32_t* a, uint32_t b0, uint32_t b1) {
    asm volatile(
        "mma.sync.aligned.m16n8k16.row.col.f32.bf16.bf16.f32 "
        "{%0,%1,%2,%3},{%4,%5,%6,%7},{%8,%9},{%0,%1,%2,%3};"
        : "+f"(d[0]), "+f"(d[1]), "+f"(d[2]), "+f"(d[3])
        : "r"(a[0]), "r"(a[1]), "r"(a[2]), "r"(a[3]), "r"(b0), "r"(b1));
}
__device__ __forceinline__ uint32_t pack_bf16x2(float x, float y) {
    __nv_bfloat162 p = __halves2bfloat162(__float2bfloat16(x), __float2bfloat16(y));
    return *reinterpret_cast<uint32_t*>(&p);
}
__device__ __forceinline__ void split2f(float x, float y, uint32_t& hi, uint32_t& lo) {
    hi = pack_bf16x2(x, y);
    __nv_bfloat162 hb = *reinterpret_cast<__nv_bfloat162*>(&hi);
    lo = pack_bf16x2(x - __low2float(hb), y - __high2float(hb));
}
__device__ __forceinline__ void split2(float2 v, uint32_t& hi, uint32_t& lo) {
    split2f(v.x, v.y, hi, lo);
}

// Exchange a float4 row segment within lane pairs (xor 1) to build mma frag pairs.
// Thread quad ownership: q0->cols0-3, q1->cols8-11, q2->cols4-7, q3->cols12-15.
// Output: f0 = cols (2q,2q+1), f1 = cols (2q+8,2q+9).
__device__ __forceinline__ void xchg_frags(float4 v, int qodd,
                                           float2& f0, float2& f1) {
    float sx = qodd ? v.x : v.z;
    float sy = qodd ? v.y : v.w;
    float rx = __shfl_xor_sync(0xFFFFFFFFu, sx, 1);
    float ry = __shfl_xor_sync(0xFFFFFFFFu, sy, 1);
    f0.x = qodd ? rx : v.x;  f0.y = qodd ? ry : v.y;
    f1.x = qodd ? v.z : rx;  f1.y = qodd ? v.w : ry;
}

// ---------------- setup (single kernel, W stays in registers) ----------------
__global__ void __launch_bounds__(256) setup_all(const float* __restrict__ qv) {
    __shared__ float qs[KREF][DDIM];
    __shared__ float G[KREF][KREF];
    __shared__ float cinv[KREF];
    int t = threadIdx.x;
    for (int i = t; i < KREF * DDIM; i += 256) qs[i >> 8][i & 255] = qv[i];
    __syncthreads();
    #pragma unroll
    for (int p = 0; p < 4; p++) {
        int idx = t + p * 256;
        int j = idx >> 5, k = idx & 31;
        float s = 0.f;
        #pragma unroll 8
        for (int d = 0; d < DDIM; d++) s = fmaf(qs[j][d], qs[k][d], s);
        G[j][k] = s;
    }
    __syncthreads();
    if (t < KREF) cinv[t] = 2.0f / G[t][t];
    __syncthreads();

    float w[KREF];
    const int d = t;
    #pragma unroll
    for (int k = 0; k < KREF; k++) {
        float acc = qs[k][d];
        #pragma unroll
        for (int j = 0; j < KREF; j++)
            if (j < k) acc = fmaf(-G[j][k], w[j], acc);
        w[k] = cinv[k] * acc;
    }
    #pragma unroll
    for (int k = 0; k < KREF; k++) {
        float wv = w[k];
        __nv_bfloat16 wh = __float2bfloat16(wv);
        g_Uh[k * DDIM + d] = wh;
        g_Ul[k * DDIM + d] = __float2bfloat16(wv - __bfloat162float(wh));
        float q = qs[k][d];
        __nv_bfloat16 qh = __float2bfloat16(q);
        g_Qh[d * KREF + k] = qh;
        g_Ql[d * KREF + k] = __float2bfloat16(q - __bfloat162float(qh));
    }
}

// ---------------- SMEM layout (bytes) ----------------
#define SB1H 0
#define SB1L 16384
#define SB2H 32768
#define SB2L 49152
#define SMEM_TOTAL 65536

__global__ void __launch_bounds__(256, 2)
hh_main(const float* __restrict__ in, float* __restrict__ out,
        long long nd, long long total) {
    extern __shared__ char smem[];
    const uint32_t sb = smem_u32(smem);
    const int tid = threadIdx.x;
    const int wid = tid >> 5, lane = tid & 31;
    const int tile = blockIdx.x;

    const float* Abase = in + (size_t)tile * MT * DDIM;
    float* Obase = out + (size_t)tile * MT * DDIM;

    // thread geometry (needed for early A prefetch)
    const int mrow = wid * 32;
    const int rl = lane >> 2;
    const int q = lane & 3;
    const int qodd = q & 1;
    const int coff = ((q & 1) << 3) | ((q >> 1) << 2);   // 0,8,4,12

    const float* Ar[2];
    Ar[0] = Abase + (size_t)(mrow + rl) * DDIM + coff;
    Ar[1] = Ar[0] + 16 * DDIM;

    // ---- early A prefetch (overlaps tail-zero + B staging below) ----
    float4 pv[2][2];   // [mb][row(0/+8)]
    #pragma unroll
    for (int mb = 0; mb < 2; mb++) {
        pv[mb][0] = *(const float4*)(Ar[mb]);
        pv[mb][1] = *(const float4*)(Ar[mb] + 8 * DDIM);
    }

    // ---- zero my slice of the tail (logabsdet), streaming stores ----
    {
        long long tail = total - nd;
        int ntile = (int)gridDim.x;
        long long per = (tail + ntile - 1) / ntile;
        long long start = nd + (long long)tile * per;
        for (long long j = tid; j < per; j += 256) {
            long long idx = start + j;
            if (idx < total) __stcs(out + idx, 0.0f);
        }
    }

    // ---- stage B1 (U hi/lo): 32x256 bf16 each ----
    #pragma unroll
    for (int i = 0; i < 8; i++) {
        int idx4 = tid + i * 256;
        int row = idx4 >> 6;
        int j4 = (idx4 & 63) << 2;
        uint32_t off = row * 512u + ((((uint32_t)(j4 >> 3)) ^ (row & 7)) << 4) + ((j4 & 4) << 1);
        *(uint2*)(smem + SB1H + off) = *(const uint2*)(g_Uh + row * DDIM + j4);
        *(uint2*)(smem + SB1L + off) = *(const uint2*)(g_Ul + row * DDIM + j4);
    }
    // ---- stage B2 (qT hi/lo): 256x32 bf16 each ----
    #pragma unroll
    for (int i = 0; i < 8; i++) {
        int idx4 = tid + i * 256;
        int row = idx4 >> 3;
        int j4 = (idx4 & 7) << 2;
        uint32_t off = row * 64u + ((((uint32_t)(j4 >> 3)) ^ ((row >> 1) & 3)) << 4) + ((j4 & 4) << 1);
        *(uint2*)(smem + SB2H + off) = *(const uint2*)(g_Qh + row * KREF + j4);
        *(uint2*)(smem + SB2L + off) = *(const uint2*)(g_Ql + row * KREF + j4);
    }
    __syncthreads();

    // ========== GEMM1: C[256x32] = A * U^T, each warp m32 (2 m16 blocks) ==========
    float accC[2][4][4];
    #pragma unroll
    for (int mb = 0; mb < 2; mb++)
        #pragma unroll
        for (int nt = 0; nt < 4; nt++)
            #pragma unroll
            for (int j = 0; j < 4; j++) accC[mb][nt][j] = 0.f;

    #pragma unroll
    for (int ks = 0; ks < 16; ks++) {
        float4 cv[2][2];
        #pragma unroll
        for (int mb = 0; mb < 2; mb++) { cv[mb][0] = pv[mb][0]; cv[mb][1] = pv[mb][1]; }
        if (ks < 15) {
            #pragma unroll
            for (int mb = 0; mb < 2; mb++) {
                pv[mb][0] = *(const float4*)(Ar[mb] + (ks + 1) * 16);
                pv[mb][1] = *(const float4*)(Ar[mb] + (ks + 1) * 16 + 8 * DDIM);
            }
        }

        uint32_t ah[2][4], al[2][4];
        #pragma unroll
        for (int mb = 0; mb < 2; mb++) {
            float2 f00, f01, f10, f11;
            xchg_frags(cv[mb][0], qodd, f00, f01);   // row r:   frag(2q), frag(2q+8)
            xchg_frags(cv[mb][1], qodd, f10, f11);   // row r+8
            split2(f00, ah[mb][0], al[mb][0]);
            split2(f10, ah[mb][1], al[mb][1]);
            split2(f01, ah[mb][2], al[mb][2]);
            split2(f11, ah[mb][3], al[mb][3]);
        }

        uint32_t bh[2][4], bl[2][4];
        #pragma unroll
        for (int t2 = 0; t2 < 2; t2++) {
            int n = t2 * 16 + (lane & 15);
            uint32_t ch = (uint32_t)(ks * 2 + (lane >> 4));
            uint32_t off = n * 512u + ((ch ^ (n & 7)) << 4);
            ldsm4(bh[t2][0], bh[t2][1], bh[t2][2], bh[t2][3], sb + SB1H + off);
            ldsm4(bl[t2][0], bl[t2][1], bl[t2][2], bl[t2][3], sb + SB1L + off);
        }
        #pragma unroll
        for (int mb = 0; mb < 2; mb++) {
            #pragma unroll
            for (int nt = 0; nt < 4; nt++) {
                const uint32_t* Bh = bh[nt >> 1];
                const uint32_t* Bl = bl[nt >> 1];
                uint32_t h0 = (nt & 1) ? Bh[1] : Bh[0], h1 = (nt & 1) ? Bh[3] : Bh[2];
                uint32_t q0 = (nt & 1) ? Bl[1] : Bl[0], q1 = (nt & 1) ? Bl[3] : Bl[2];
                mma16816(accC[mb][nt], ah[mb], h0, h1);
                mma16816(accC[mb][nt], ah[mb], q0, q1);
                mma16816(accC[mb][nt], al[mb], h0, h1);
            }
        }
    }

    // ---- repack C (acc layout == GEMM2 A-fragment layout, k = n) ----
    uint32_t ch[2][2][4], cl[2][2][4];
    #pragma unroll
    for (int mb = 0; mb < 2; mb++) {
        #pragma unroll
        for (int kb = 0; kb < 2; kb++) {
            split2f(accC[mb][kb * 2][0],     accC[mb][kb * 2][1],     ch[mb][kb][0], cl[mb][kb][0]);
            split2f(accC[mb][kb * 2][2],     accC[mb][kb * 2][3],     ch[mb][kb][1], cl[mb][kb][1]);
            split2f(accC[mb][kb * 2 + 1][0], accC[mb][kb * 2 + 1][1], ch[mb][kb][2], cl[mb][kb][2]);
            split2f(accC[mb][kb * 2 + 1][2], accC[mb][kb * 2 + 1][3], ch[mb][kb][3], cl[mb][kb][3]);
        }
    }

    // ========== GEMM2 + epilogue: out = A - C * Q^T ==========
    // Epilogue A double-buffered: load for nc16+1 issued a full mma-block early.
    float4 av[2][2][2];   // [buf][mb][h]
    #pragma unroll
    for (int mb = 0; mb < 2; mb++) {
        #pragma unroll
        for (int h = 0; h < 2; h++) {
            int r = mrow + mb * 16 + rl + h * 8;
            av[0][mb][h] = __ldcs((const float4*)(Abase + (size_t)r * DDIM + coff));
        }
    }

    #pragma unroll 1
    for (int nc16 = 0; nc16 < 16; nc16++) {
        const int cur = nc16 & 1;
        // prefetch next chunk (distance 1 = one full mma block ahead)
        if (nc16 < 15) {
            #pragma unroll
            for (int mb = 0; mb < 2; mb++) {
                #pragma unroll
                for (int h = 0; h < 2; h++) {
                    int r = mrow + mb * 16 + rl + h * 8;
                    av[cur ^ 1][mb][h] = __ldcs(
                        (const float4*)(Abase + (size_t)r * DDIM + (nc16 + 1) * 16 + coff));
                }
            }
        }

        float acc[2][2][4];
        #pragma unroll
        for (int mb = 0; mb < 2; mb++)
            #pragma unroll
            for (int nt = 0; nt < 2; nt++)
                #pragma unroll
                for (int j = 0; j < 4; j++) acc[mb][nt][j] = 0.f;

        #pragma unroll
        for (int kb = 0; kb < 2; kb++) {
            uint32_t bh[4], bl[4];
            int n = nc16 * 16 + (lane & 15);
            uint32_t chn = (uint32_t)(kb * 2 + (lane >> 4));
            uint32_t off = n * 64u + ((chn ^ ((n >> 1) & 3)) << 4);
            ldsm4(bh[0], bh[1], bh[2], bh[3], sb + SB2H + off);
            ldsm4(bl[0], bl[1], bl[2], bl[3], sb + SB2L + off);
            #pragma unroll
            for (int mb = 0; mb < 2; mb++) {
                #pragma unroll
                for (int nt = 0; nt < 2; nt++) {
                    uint32_t h0 = nt ? bh[1] : bh[0], h1 = nt ? bh[3] : bh[2];
                    uint32_t q0 = nt ? bl[1] : bl[0], q1 = nt ? bl[3] : bl[2];
                    mma16816(acc[mb][nt], ch[mb][kb], h0, h1);
                    mma16816(acc[mb][nt], ch[mb][kb], q0, q1);
                    mma16816(acc[mb][nt], cl[mb][kb], h0, h1);
                }
            }
        }
        // epilogue: shfl exchange + subtract + float4 streaming store via shfl gather
        #pragma unroll
        for (int mb = 0; mb < 2; mb++) {
            #pragma unroll
            for (int h = 0; h < 2; h++) {
                int r = mrow + mb * 16 + rl + h * 8;
                float2 a0, a1;
                xchg_frags(av[cur][mb][h], qodd, a0, a1);
                float o0x = a0.x - acc[mb][0][h * 2 + 0];
                float o0y = a0.y - acc[mb][0][h * 2 + 1];
                float o1x = a1.x - acc[mb][1][h * 2 + 0];
                float o1y = a1.y - acc[mb][1][h * 2 + 1];
                float tx = qodd ? o0x : o1x;
                float ty = qodd ? o0y : o1y;
                float ux = __shfl_xor_sync(0xFFFFFFFFu, tx, 1);
                float uy = __shfl_xor_sync(0xFFFFFFFFu, ty, 1);
                float4 o;
                o.x = qodd ? ux : o0x;
                o.y = qodd ? uy : o0y;
                o.z = qodd ? o1x : ux;
                o.w = qodd ? o1y : uy;
                __stcs((float4*)(Obase + (size_t)r * DDIM + nc16 * 16 + coff), o);
            }
        }
    }
}

extern "C" void kernel_launch(void* const* d_in, const int* in_sizes, int n_in,
                              void* d_out, int out_size) {
    const float* inp = (const float*)d_in[0];   // inputs  [N, 256]
    const float* qv  = (const float*)d_in[1];   // q_vectors [32, 256]
    float* out = (float*)d_out;

    int n_rows = in_sizes[0] / DDIM;
    int n_tiles = n_rows / MT;

    cudaFuncSetAttribute(hh_main, cudaFuncAttributeMaxDynamicSharedMemorySize, SMEM_TOTAL);

    long long nd = (long long)n_rows * DDIM;
    long long total = (long long)out_size;

    setup_all<<<1, 256>>>(qv);
    hh_main<<<n_tiles, 256, SMEM_TOTAL>>>(inp, out, nd, total);
}

// round 15
// speedup vs baseline: 1.5182x; 1.5182x over previous
#include <cuda_runtime.h>
#include <cuda_bf16.h>
#include <cstdint>

#define DDIM 256
#define KREF 32
#define MT   256    // rows per CTA (8 warps x m32)

// ---------------- device scratch (no allocation) ----------------
__device__ __align__(16) __nv_bfloat16 g_Uh[KREF * DDIM];   // [k][d]
__device__ __align__(16) __nv_bfloat16 g_Ul[KREF * DDIM];
__device__ __align__(16) __nv_bfloat16 g_Qh[DDIM * KREF];   // [d][k]
__device__ __align__(16) __nv_bfloat16 g_Ql[DDIM * KREF];

// ---------------- helpers ----------------
__device__ __forceinline__ uint32_t smem_u32(const void* p) {
    uint32_t a;
    asm("{ .reg .u64 t; cvta.to.shared.u64 t, %1; cvt.u32.u64 %0, t; }" : "=r"(a) : "l"(p));
    return a;
}
__device__ __forceinline__ void ldsm4(uint32_t& r0, uint32_t& r1, uint32_t& r2, uint32_t& r3,
                                      uint32_t addr) {
    asm volatile("ldmatrix.sync.aligned.m8n8.x4.shared.b16 {%0,%1,%2,%3}, [%4];"
                 : "=r"(r0), "=r"(r1), "=r"(r2), "=r"(r3) : "r"(addr));
}
__device__ __forceinline__ void mma16816(float* d, const uint32_t* a, uint32_t b0, uint32_t b1) {
    asm volatile(
        "mma.sync.aligned.m16n8k16.row.col.f32.bf16.bf16.f32 "
        "{%0,%1,%2,%3},{%4,%5,%6,%7},{%8,%9},{%0,%1,%2,%3};"
        : "+f"(d[0]), "+f"(d[1]), "+f"(d[2]), "+f"(d[3])
        : "r"(a[0]), "r"(a[1]), "r"(a[2]), "r"(a[3]), "r"(b0), "r"(b1));
}
__device__ __forceinline__ uint32_t pack_bf16x2(float x, float y) {
    __nv_bfloat162 p = __halves2bfloat162(__float2bfloat16(x), __float2bfloat16(y));
    return *reinterpret_cast<uint32_t*>(&p);
}
__device__ __forceinline__ void split2f(float x, float y, uint32_t& hi, uint32_t& lo) {
    hi = pack_bf16x2(x, y);
    __nv_bfloat162 hb = *reinterpret_cast<__nv_bfloat162*>(&hi);
    lo = pack_bf16x2(x - __low2float(hb), y - __high2float(hb));
}
__device__ __forceinline__ void split2(float2 v, uint32_t& hi, uint32_t& lo) {
    split2f(v.x, v.y, hi, lo);
}

// Exchange a float4 row segment within lane pairs (xor 1) to build mma frag pairs.
// Thread quad ownership: q0->cols0-3, q1->cols8-11, q2->cols4-7, q3->cols12-15.
// Output: f0 = cols (2q,2q+1), f1 = cols (2q+8,2q+9).
__device__ __forceinline__ void xchg_frags(float4 v, int qodd,
                                           float2& f0, float2& f1) {
    float sx = qodd ? v.x : v.z;
    float sy = qodd ? v.y : v.w;
    float rx = __shfl_xor_sync(0xFFFFFFFFu, sx, 1);
    float ry = __shfl_xor_sync(0xFFFFFFFFu, sy, 1);
    f0.x = qodd ? rx : v.x;  f0.y = qodd ? ry : v.y;
    f1.x = qodd ? v.z : rx;  f1.y = qodd ? v.w : ry;
}

// ---------------- setup (single kernel, W stays in registers) ----------------
// qs padded to DDIM+1: row stride 257 floats -> bank stride 1 -> the Gram loop's
// lane-indexed qs[k][d] reads are conflict-free (unpadded: 32-way conflict).
__global__ void __launch_bounds__(256) setup_all(const float* __restrict__ qv) {
    __shared__ float qs[KREF][DDIM + 1];
    __shared__ float G[KREF][KREF];
    __shared__ float cinv[KREF];
    int t = threadIdx.x;
    for (int i = t; i < KREF * DDIM; i += 256) qs[i >> 8][i & 255] = qv[i];
    __syncthreads();
    #pragma unroll
    for (int p = 0; p < 4; p++) {
        int idx = t + p * 256;
        int j = idx >> 5, k = idx & 31;
        float s = 0.f;
        #pragma unroll 8
        for (int d = 0; d < DDIM; d++) s = fmaf(qs[j][d], qs[k][d], s);
        G[j][k] = s;
    }
    __syncthreads();
    if (t < KREF) cinv[t] = 2.0f / G[t][t];
    __syncthreads();

    float w[KREF];
    const int d = t;
    #pragma unroll
    for (int k = 0; k < KREF; k++) {
        float acc = qs[k][d];
        #pragma unroll
        for (int j = 0; j < KREF; j++)
            if (j < k) acc = fmaf(-G[j][k], w[j], acc);
        w[k] = cinv[k] * acc;
    }
    #pragma unroll
    for (int k = 0; k < KREF; k++) {
        float wv = w[k];
        __nv_bfloat16 wh = __float2bfloat16(wv);
        g_Uh[k * DDIM + d] = wh;
        g_Ul[k * DDIM + d] = __float2bfloat16(wv - __bfloat162float(wh));
        float q = qs[k][d];
        __nv_bfloat16 qh = __float2bfloat16(q);
        g_Qh[d * KREF + k] = qh;
        g_Ql[d * KREF + k] = __float2bfloat16(q - __bfloat162float(qh));
    }
}

// ---------------- SMEM layout (bytes) ----------------
#define SB1H 0
#define SB1L 16384
#define SB2H 32768
#define SB2L 49152
#define SMEM_TOTAL 65536

__global__ void __launch_bounds__(256, 2)
hh_main(const float* __restrict__ in, float* __restrict__ out,
        long long nd, long long total) {
    extern __shared__ char smem[];
    const uint32_t sb = smem_u32(smem);
    const int tid = threadIdx.x;
    const int wid = tid >> 5, lane = tid & 31;
    const int tile = blockIdx.x;

    const float* Abase = in + (size_t)tile * MT * DDIM;
    float* Obase = out + (size_t)tile * MT * DDIM;

    // ---- zero my slice of the tail (logabsdet) ----
    {
        long long tail = total - nd;
        int ntile = (int)gridDim.x;
        long long per = (tail + ntile - 1) / ntile;
        long long start = nd + (long long)tile * per;
        for (long long j = tid; j < per; j += 256) {
            long long idx = start + j;
            if (idx < total) out[idx] = 0.0f;
        }
    }

    // ---- stage B1 (U hi/lo): 32x256 bf16 each ----
    #pragma unroll
    for (int i = 0; i < 8; i++) {
        int idx4 = tid + i * 256;
        int row = idx4 >> 6;
        int j4 = (idx4 & 63) << 2;
        uint32_t off = row * 512u + ((((uint32_t)(j4 >> 3)) ^ (row & 7)) << 4) + ((j4 & 4) << 1);
        *(uint2*)(smem + SB1H + off) = *(const uint2*)(g_Uh + row * DDIM + j4);
        *(uint2*)(smem + SB1L + off) = *(const uint2*)(g_Ul + row * DDIM + j4);
    }
    // ---- stage B2 (qT hi/lo): 256x32 bf16 each ----
    #pragma unroll
    for (int i = 0; i < 8; i++) {
        int idx4 = tid + i * 256;
        int row = idx4 >> 3;
        int j4 = (idx4 & 7) << 2;
        uint32_t off = row * 64u + ((((uint32_t)(j4 >> 3)) ^ ((row >> 1) & 3)) << 4) + ((j4 & 4) << 1);
        *(uint2*)(smem + SB2H + off) = *(const uint2*)(g_Qh + row * KREF + j4);
        *(uint2*)(smem + SB2L + off) = *(const uint2*)(g_Ql + row * KREF + j4);
    }
    __syncthreads();

    // ========== GEMM1: C[256x32] = A * U^T, each warp m32 (2 m16 blocks) ==========
    const int mrow = wid * 32;
    const int rl = lane >> 2;
    const int q = lane & 3;
    const int qodd = q & 1;
    const int coff = ((q & 1) << 3) | ((q >> 1) << 2);   // 0,8,4,12

    const float* Ar[2];
    Ar[0] = Abase + (size_t)(mrow + rl) * DDIM + coff;
    Ar[1] = Ar[0] + 16 * DDIM;

    float accC[2][4][4];
    #pragma unroll
    for (int mb = 0; mb < 2; mb++)
        #pragma unroll
        for (int nt = 0; nt < 4; nt++)
            #pragma unroll
            for (int j = 0; j < 4; j++) accC[mb][nt][j] = 0.f;

    float4 pv[2][2];   // [mb][row(0/+8)]
    #pragma unroll
    for (int mb = 0; mb < 2; mb++) {
        pv[mb][0] = *(const float4*)(Ar[mb]);
        pv[mb][1] = *(const float4*)(Ar[mb] + 8 * DDIM);
    }

    #pragma unroll
    for (int ks = 0; ks < 16; ks++) {
        float4 cv[2][2];
        #pragma unroll
        for (int mb = 0; mb < 2; mb++) { cv[mb][0] = pv[mb][0]; cv[mb][1] = pv[mb][1]; }
        if (ks < 15) {
            #pragma unroll
            for (int mb = 0; mb < 2; mb++) {
                pv[mb][0] = *(const float4*)(Ar[mb] + (ks + 1) * 16);
                pv[mb][1] = *(const float4*)(Ar[mb] + (ks + 1) * 16 + 8 * DDIM);
            }
        }

        uint32_t ah[2][4], al[2][4];
        #pragma unroll
        for (int mb = 0; mb < 2; mb++) {
            float2 f00, f01, f10, f11;
            xchg_frags(cv[mb][0], qodd, f00, f01);   // row r:   frag(2q), frag(2q+8)
            xchg_frags(cv[mb][1], qodd, f10, f11);   // row r+8
            split2(f00, ah[mb][0], al[mb][0]);
            split2(f10, ah[mb][1], al[mb][1]);
            split2(f01, ah[mb][2], al[mb][2]);
            split2(f11, ah[mb][3], al[mb][3]);
        }

        uint32_t bh[2][4], bl[2][4];
        #pragma unroll
        for (int t2 = 0; t2 < 2; t2++) {
            int n = t2 * 16 + (lane & 15);
            uint32_t ch = (uint32_t)(ks * 2 + (lane >> 4));
            uint32_t off = n * 512u + ((ch ^ (n & 7)) << 4);
            ldsm4(bh[t2][0], bh[t2][1], bh[t2][2], bh[t2][3], sb + SB1H + off);
            ldsm4(bl[t2][0], bl[t2][1], bl[t2][2], bl[t2][3], sb + SB1L + off);
        }
        #pragma unroll
        for (int mb = 0; mb < 2; mb++) {
            #pragma unroll
            for (int nt = 0; nt < 4; nt++) {
                const uint32_t* Bh = bh[nt >> 1];
                const uint32_t* Bl = bl[nt >> 1];
                uint32_t h0 = (nt & 1) ? Bh[1] : Bh[0], h1 = (nt & 1) ? Bh[3] : Bh[2];
                uint32_t q0 = (nt & 1) ? Bl[1] : Bl[0], q1 = (nt & 1) ? Bl[3] : Bl[2];
                mma16816(accC[mb][nt], ah[mb], h0, h1);
                mma16816(accC[mb][nt], ah[mb], q0, q1);
                mma16816(accC[mb][nt], al[mb], h0, h1);
            }
        }
    }

    // ---- repack C (acc layout == GEMM2 A-fragment layout, k = n) ----
    uint32_t ch[2][2][4], cl[2][2][4];
    #pragma unroll
    for (int mb = 0; mb < 2; mb++) {
        #pragma unroll
        for (int kb = 0; kb < 2; kb++) {
            split2f(accC[mb][kb * 2][0],     accC[mb][kb * 2][1],     ch[mb][kb][0], cl[mb][kb][0]);
            split2f(accC[mb][kb * 2][2],     accC[mb][kb * 2][3],     ch[mb][kb][1], cl[mb][kb][1]);
            split2f(accC[mb][kb * 2 + 1][0], accC[mb][kb * 2 + 1][1], ch[mb][kb][2], cl[mb][kb][2]);
            split2f(accC[mb][kb * 2 + 1][2], accC[mb][kb * 2 + 1][3], ch[mb][kb][3], cl[mb][kb][3]);
        }
    }

    // ========== GEMM2 + epilogue: out = A - C * Q^T ==========
    #pragma unroll 1
    for (int nc16 = 0; nc16 < 16; nc16++) {
        float acc[2][2][4];
        #pragma unroll
        for (int mb = 0; mb < 2; mb++)
            #pragma unroll
            for (int nt = 0; nt < 2; nt++)
                #pragma unroll
                for (int j = 0; j < 4; j++) acc[mb][nt][j] = 0.f;

        // prefetch epilogue A chunk
        float4 av[2][2];
        #pragma unroll
        for (int mb = 0; mb < 2; mb++) {
            #pragma unroll
            for (int h = 0; h < 2; h++) {
                int r = mrow + mb * 16 + rl + h * 8;
                av[mb][h] = *(const float4*)(Abase + (size_t)r * DDIM + nc16 * 16 + coff);
            }
        }

        #pragma unroll
        for (int kb = 0; kb < 2; kb++) {
            uint32_t bh[4], bl[4];
            int n = nc16 * 16 + (lane & 15);
            uint32_t chn = (uint32_t)(kb * 2 + (lane >> 4));
            uint32_t off = n * 64u + ((chn ^ ((n >> 1) & 3)) << 4);
            ldsm4(bh[0], bh[1], bh[2], bh[3], sb + SB2H + off);
            ldsm4(bl[0], bl[1], bl[2], bl[3], sb + SB2L + off);
            #pragma unroll
            for (int mb = 0; mb < 2; mb++) {
                #pragma unroll
                for (int nt = 0; nt < 2; nt++) {
                    uint32_t h0 = nt ? bh[1] : bh[0], h1 = nt ? bh[3] : bh[2];
                    uint32_t q0 = nt ? bl[1] : bl[0], q1 = nt ? bl[3] : bl[2];
                    mma16816(acc[mb][nt], ch[mb][kb], h0, h1);
                    mma16816(acc[mb][nt], ch[mb][kb], q0, q1);
                    mma16816(acc[mb][nt], cl[mb][kb], h0, h1);
                }
            }
        }
        // epilogue: shfl exchange + subtract + float4 store via shfl gather
        #pragma unroll
        for (int mb = 0; mb < 2; mb++) {
            #pragma unroll
            for (int h = 0; h < 2; h++) {
                int r = mrow + mb * 16 + rl + h * 8;
                float2 a0, a1;
                xchg_frags(av[mb][h], qodd, a0, a1);
                float o0x = a0.x - acc[mb][0][h * 2 + 0];
                float o0y = a0.y - acc[mb][0][h * 2 + 1];
                float o1x = a1.x - acc[mb][1][h * 2 + 0];
                float o1y = a1.y - acc[mb][1][h * 2 + 1];
                float tx = qodd ? o0x : o1x;
                float ty = qodd ? o0y : o1y;
                float ux = __shfl_xor_sync(0xFFFFFFFFu, tx, 1);
                float uy = __shfl_xor_sync(0xFFFFFFFFu, ty, 1);
                float4 o;
                o.x = qodd ? ux : o0x;
                o.y = qodd ? uy : o0y;
                o.z = qodd ? o1x : ux;
                o.w = qodd ? o1y : uy;
                *(float4*)(Obase + (size_t)r * DDIM + nc16 * 16 + coff) = o;
            }
        }
    }
}

extern "C" void kernel_launch(void* const* d_in, const int* in_sizes, int n_in,
                              void* d_out, int out_size) {
    const float* inp = (const float*)d_in[0];   // inputs  [N, 256]
    const float* qv  = (const float*)d_in[1];   // q_vectors [32, 256]
    float* out = (float*)d_out;

    int n_rows = in_sizes[0] / DDIM;
    int n_tiles = n_rows / MT;

    cudaFuncSetAttribute(hh_main, cudaFuncAttributeMaxDynamicSharedMemorySize, SMEM_TOTAL);

    long long nd = (long long)n_rows * DDIM;
    long long total = (long long)out_size;

    setup_all<<<1, 256>>>(qv);
    hh_main<<<n_tiles, 256, SMEM_TOTAL>>>(inp, out, nd, total);
}